// round 17
// baseline (speedup 1.0000x reference)
#include <cuda_runtime.h>
#include <math.h>

#define NN      256      // neurons
#define NSAMP   512      // samples
#define NROUND  32       // MAX_SPIKES rounds
#define NSTEP   32       // RK4 steps per round
#define NPER    8        // neurons per thread
#define NPAIR   4        // f32x2 pairs per thread
#define WPB     4        // warps (= samples) per block

// flattened output offsets (all float32)
#define OUT_TIMES 0
#define OUT_VALS  (NSAMP * NROUND)                       // 16384
#define OUT_MARKS (OUT_VALS + NSAMP * NROUND * NN * 3)   // 12599296

#define NEG_LOG2E (-1.4426950408889634f)

typedef unsigned long long u64;

// ---- packed f32x2 primitives (element-wise IEEE rn == scalar ops) ----
__device__ __forceinline__ u64 pk2(float lo, float hi) {
    u64 r;
    asm("mov.b64 %0, {%1, %2};" : "=l"(r)
        : "r"(__float_as_uint(lo)), "r"(__float_as_uint(hi)));
    return r;
}
__device__ __forceinline__ void upk2(u64 p, float& lo, float& hi) {
    unsigned a, b;
    asm("mov.b64 {%0, %1}, %2;" : "=r"(a), "=r"(b) : "l"(p));
    lo = __uint_as_float(a); hi = __uint_as_float(b);
}
__device__ __forceinline__ u64 fma2(u64 a, u64 b, u64 c) {
    u64 r; asm("fma.rn.f32x2 %0, %1, %2, %3;" : "=l"(r) : "l"(a), "l"(b), "l"(c)); return r;
}
__device__ __forceinline__ u64 mul2(u64 a, u64 b) {
    u64 r; asm("mul.rn.f32x2 %0, %1, %2;" : "=l"(r) : "l"(a), "l"(b)); return r;
}
__device__ __forceinline__ u64 add2(u64 a, u64 b) {
    u64 r; asm("add.rn.f32x2 %0, %1, %2;" : "=l"(r) : "l"(a), "l"(b)); return r;
}

__device__ __forceinline__ float ex2_approx(float x) {
    float r;
    asm("ex2.approx.ftz.f32 %0, %1;" : "=f"(r) : "f"(x));
    return r;
}

// coefficient triple: value = .v * v0 + .i * i0 + .c * icn
struct C3 { float v, i, c; };
__device__ __forceinline__ C3 c3(float a, float b, float c) { return {a, b, c}; }
__device__ __forceinline__ C3 add(C3 a, C3 b) { return {a.v + b.v, a.i + b.i, a.c + b.c}; }
__device__ __forceinline__ C3 sub(C3 a, C3 b) { return {a.v - b.v, a.i - b.i, a.c - b.c}; }
__device__ __forceinline__ C3 scl(float s, C3 a) { return {s * a.v, s * a.i, s * a.c}; }

__global__ __launch_bounds__(WPB * 32)
void snn_kernel(const float* __restrict__ ic,      // [256]
                const float* __restrict__ w,       // [256,256]
                const float* __restrict__ mu,      // [2]
                const float* __restrict__ v0g,     // [256]
                const float* __restrict__ i0g,     // [256]
                const float* __restrict__ s0g,     // [512,256]
                const float* __restrict__ reset_s, // [32,512,256]
                const int*   __restrict__ t1p,     // scalar
                float* __restrict__ out)
{
    const int lane = threadIdx.x & 31;
    const int wid  = threadIdx.x >> 5;
    const int samp = blockIdx.x * WPB + wid;   // one warp == one sample

    const float t1f = (float)(*t1p);
    const float mu1 = mu[0];
    const float mu2 = mu[1];

    // thread owns neurons n = lane + 32*j, j in [0,8); pair q holds j = 2q, 2q+1
    float icn[NPER];
    float v[NPER], iC[NPER], s[NPER];
    #pragma unroll
    for (int j = 0; j < NPER; ++j) {
        const int n = lane + 32 * j;
        icn[j] = ic[n];
        v[j]   = v0g[n];
        iC[j]  = i0g[n];
        s[j]   = s0g[samp * NN + n];
    }
    // packed state
    u64 vP[NPAIR], iP[NPAIR], sP[NPAIR];
    #pragma unroll
    for (int q = 0; q < NPAIR; ++q) {
        vP[q] = pk2(v[2*q], v[2*q+1]);
        iP[q] = pk2(iC[2*q], iC[2*q+1]);
        sP[q] = pk2(s[2*q], s[2*q+1]);
    }
    float t0s = 0.0f;

    for (int k = 0; k < NROUND; ++k) {
        const float dt = (t1f - t0s) * (1.0f / (float)NSTEP);
        const float h6s = dt * (1.0f / 6.0f);

        // prefetch the reset row for this round off the critical path
        float rsk[NPER];
        #pragma unroll
        for (int j = 0; j < NPER; ++j)
            rsk[j] = reset_s[(size_t)k * NSAMP * NN + samp * NN + lane + 32 * j];

        int      trig = 0;
        float    tev  = t1f;
        unsigned emk  = 0;
        float    wr[NPER];
        #pragma unroll
        for (int j = 0; j < NPER; ++j) wr[j] = 0.0f;

        u64 vnP[NPAIR], inP[NPAIR], numP[NPAIR], denP[NPAIR];
        float tcur = t0s;

        if (dt > 0.0f) {
            const float h  = dt;
            const float hh = 0.5f * h;
            const float h6 = h6s;

            // ---- per-round affine RK4 stage coefficients (warp-uniform) ----
            const C3 V   = c3(1.f, 0.f, 0.f);
            const C3 I   = c3(0.f, 1.f, 0.f);
            const C3 ONE = c3(0.f, 0.f, 1.f);
            C3 k1v = scl(mu1, sub(add(I, ONE), V));
            C3 k1i = scl(-mu2, I);
            C3 v2c = add(V, scl(hh, k1v));
            C3 i2c = add(I, scl(hh, k1i));
            C3 k2v = scl(mu1, sub(add(i2c, ONE), v2c));
            C3 k2i = scl(-mu2, i2c);
            C3 v3c = add(V, scl(hh, k2v));
            C3 i3c = add(I, scl(hh, k2i));
            C3 k3v = scl(mu1, sub(add(i3c, ONE), v3c));
            C3 k3i = scl(-mu2, i3c);
            C3 v4c = add(V, scl(h, k3v));
            C3 i4c = add(I, scl(h, k3i));
            C3 k4v = scl(mu1, sub(add(i4c, ONE), v4c));
            C3 k4i = scl(-mu2, i4c);
            C3 vnc = add(V, scl(h6, add(add(k1v, k4v), scl(2.f, add(k2v, k3v)))));
            C3 inc = add(I, scl(h6, add(add(k1i, k4i), scl(2.f, add(k2i, k3i)))));
            const float pin = inc.i;

            const float a2 = NEG_LOG2E * v2c.v, b2 = NEG_LOG2E * v2c.i;
            const float a3 = NEG_LOG2E * v3c.v, b3 = NEG_LOG2E * v3c.i;
            const float a4 = NEG_LOG2E * v4c.v, b4 = NEG_LOG2E * v4c.i;

            // packed broadcast constants
            const u64 A2 = pk2(a2, a2), B2 = pk2(b2, b2);
            const u64 A3 = pk2(a3, a3), B3 = pk2(b3, b3);
            const u64 A4 = pk2(a4, a4), B4 = pk2(b4, b4);
            const u64 VNV = pk2(vnc.v, vnc.v), VNI = pk2(vnc.i, vnc.i);
            const u64 PIN = pk2(pin, pin);
            const u64 NL  = pk2(NEG_LOG2E, NEG_LOG2E);
            const u64 ONE2 = pk2(1.0f, 1.0f);
            const u64 H6P  = pk2(h6, h6);

            u64 U2CC[NPAIR], U3CC[NPAIR], U4CC[NPAIR], VNCC[NPAIR];
            const float c2 = NEG_LOG2E * v2c.c, cc3 = NEG_LOG2E * v3c.c;
            const float c4 = NEG_LOG2E * v4c.c;
            #pragma unroll
            for (int q = 0; q < NPAIR; ++q) {
                U2CC[q] = pk2(c2 * icn[2*q],    c2 * icn[2*q+1]);
                U3CC[q] = pk2(cc3 * icn[2*q],   cc3 * icn[2*q+1]);
                U4CC[q] = pk2(c4 * icn[2*q],    c4 * icn[2*q+1]);
                VNCC[q] = pk2(vnc.c * icn[2*q], vnc.c * icn[2*q+1]);
            }

            for (int st = 0; st < NSTEP; ++st) {
                // ---- RK4 step: front-end + DIV-FREE trigger predicate ----
                // sn2 = s + h6*num/den with den = p14*p23 >= 1 > 0, so
                //   sn2 > 0  <=>  h6*num + s*den > 0   (one fma2, no RCP)
                // The division is issued only AFTER the vote.
                float mx = -INFINITY;
                #pragma unroll
                for (int q = 0; q < NPAIR; ++q) {
                    const u64 vq = vP[q], iq = iP[q];
                    u64 u1 = mul2(NL, vq);
                    u64 u2 = fma2(A2, vq, fma2(B2, iq, U2CC[q]));
                    u64 u3 = fma2(A3, vq, fma2(B3, iq, U3CC[q]));
                    u64 u4 = fma2(A4, vq, fma2(B4, iq, U4CC[q]));
                    vnP[q] = fma2(VNV, vq, fma2(VNI, iq, VNCC[q]));
                    inP[q] = mul2(PIN, iq);
                    float x1a, x1b, x2a, x2b, x3a, x3b, x4a, x4b;
                    upk2(u1, x1a, x1b); upk2(u2, x2a, x2b);
                    upk2(u3, x3a, x3b); upk2(u4, x4a, x4b);
                    u64 e1 = pk2(ex2_approx(x1a), ex2_approx(x1b));
                    u64 e2 = pk2(ex2_approx(x2a), ex2_approx(x2b));
                    u64 e3 = pk2(ex2_approx(x3a), ex2_approx(x3b));
                    u64 e4 = pk2(ex2_approx(x4a), ex2_approx(x4b));
                    u64 t1_ = add2(ONE2, e1), t2_ = add2(ONE2, e2);
                    u64 t3_ = add2(ONE2, e3), t4_ = add2(ONE2, e4);
                    u64 p14 = mul2(t1_, t4_), p23 = mul2(t2_, t3_);
                    u64 s14 = add2(t1_, t4_), s23 = add2(t2_, t3_);
                    u64 num = fma2(s14, p23, mul2(add2(s23, s23), p14));
                    u64 den = mul2(p14, p23);
                    numP[q] = num; denP[q] = den;
                    u64 pr = fma2(H6P, num, mul2(sP[q], den));
                    float pa, pb;
                    upk2(pr, pa, pb);
                    mx = fmaxf(mx, fmaxf(pa, pb));
                }

                // ---- trigger check: single warp vote, no barrier ----
                trig = __any_sync(0xffffffffu, mx > 0.0f);
                if (trig) break;

                // ---- commit (divs post-vote; latency drains into the next
                //      step's front-end, which does not consume s) ----
                #pragma unroll
                for (int q = 0; q < NPAIR; ++q) {
                    float na, nb, da, db;
                    upk2(numP[q], na, nb); upk2(denP[q], da, db);
                    float ca = __fdividef(na, da);
                    float cb = __fdividef(nb, db);
                    sP[q] = fma2(H6P, pk2(ca, cb), sP[q]);
                    vP[q] = vnP[q]; iP[q] = inP[q];
                }
                tcur += dt;
            }
        }

        // ---- scalarize state (prev) ----
        #pragma unroll
        for (int q = 0; q < NPAIR; ++q) {
            upk2(vP[q], v[2*q], v[2*q+1]);
            upk2(iP[q], iC[2*q], iC[2*q+1]);
            upk2(sP[q], s[2*q], s[2*q+1]);
        }

        if (trig) {
            // reconstruct sn2 with the IDENTICAL __fdividef + fma2 sequence the
            // commit path uses -> values bit-identical to R16
            float vn[NPER], in2[NPER], sn2[NPER];
            const u64 H6P2 = pk2(h6s, h6s);
            #pragma unroll
            for (int q = 0; q < NPAIR; ++q) {
                upk2(vnP[q], vn[2*q], vn[2*q+1]);
                upk2(inP[q], in2[2*q], in2[2*q+1]);
                float na, nb, da, db;
                upk2(numP[q], na, nb); upk2(denP[q], da, db);
                float ca = __fdividef(na, da);
                float cb = __fdividef(nb, db);
                float s2a, s2b;
                upk2(fma2(H6P2, pk2(ca, cb), sP[q]), s2a, s2b);
                sn2[2*q] = s2a; sn2[2*q+1] = s2b;
            }

            // local argmax over own 8 neurons (ascending j + strict > keeps the
            // lowest index on ties, matching jnp.argmax) + local min spiking idx
            float rv = sn2[0], rp = s[0];
            int   ri = lane;
            int   rm = (sn2[0] > 0.0f) ? lane : NN;
            #pragma unroll
            for (int j = 1; j < NPER; ++j) {
                const int n = lane + 32 * j;
                if (sn2[j] > rv) { rv = sn2[j]; rp = s[j]; ri = n; }
                if (sn2[j] > 0.0f) rm = min(rm, n);
            }
            // warp butterfly: every lane ends with the full result
            #pragma unroll
            for (int o = 16; o > 0; o >>= 1) {
                float ov = __shfl_xor_sync(0xffffffffu, rv, o);
                float op = __shfl_xor_sync(0xffffffffu, rp, o);
                int   oi = __shfl_xor_sync(0xffffffffu, ri, o);
                int   om = __shfl_xor_sync(0xffffffffu, rm, o);
                if (ov > rv || (ov == rv && oi < ri)) { rv = ov; rp = op; ri = oi; }
                rm = min(rm, om);
            }

            // issue the w-row loads NOW (L2-hot) so their latency hides under
            // the frac math + output stores below
            #pragma unroll
            for (int j = 0; j < NPER; ++j)
                wr[j] = w[rm * NN + lane + 32 * j];

            float fr = rp / (rp - rv + 1e-12f);
            fr  = fminf(fmaxf(fr, 0.0f), 1.0f);
            tev = tcur + fr * dt;
            #pragma unroll
            for (int j = 0; j < NPER; ++j) {
                v[j]  = v[j]  + fr * (vn[j]  - v[j]);
                iC[j] = iC[j] + fr * (in2[j] - iC[j]);
                s[j]  = s[j]  + fr * (sn2[j] - s[j]);
                if (sn2[j] > 0.0f) emk |= (1u << j);
            }
        }

        // ---- outputs + reset for this round (v/iC/s currently == yev) ----
        if (lane == 0) out[OUT_TIMES + samp * NROUND + k] = tev;
        const size_t base = (size_t)(samp * NROUND + k) * NN;
        #pragma unroll
        for (int j = 0; j < NPER; ++j) {
            const int n = lane + 32 * j;
            float* vp = out + OUT_VALS + (base + n) * 3;
            vp[0] = v[j]; vp[1] = iC[j]; vp[2] = s[j];
            const bool em = (emk >> j) & 1u;
            out[OUT_MARKS + base + n] = em ? 1.0f : 0.0f;
            v[j]  = v[j] - (em ? 1.0f : 0.0f);
            iC[j] = iC[j] + wr[j];
            const float srs = em ? rsk[j] : s[j];
            s[j]  = fminf(srs, 0.0f);
        }
        // repack state for next round
        #pragma unroll
        for (int q = 0; q < NPAIR; ++q) {
            vP[q] = pk2(v[2*q], v[2*q+1]);
            iP[q] = pk2(iC[2*q], iC[2*q+1]);
            sP[q] = pk2(s[2*q], s[2*q+1]);
        }
        t0s = tev;
    }
}

extern "C" void kernel_launch(void* const* d_in, const int* in_sizes, int n_in,
                              void* d_out, int out_size) {
    const float* ic      = (const float*)d_in[0];  // input_current [256]
    const float* w       = (const float*)d_in[1];  // w [256,256]
    const float* mu      = (const float*)d_in[2];  // mu [2]
    const float* v0      = (const float*)d_in[3];  // v0 [256]
    const float* i0      = (const float*)d_in[4];  // i0 [256]
    const float* s0      = (const float*)d_in[5];  // s0 [512,256]
    const float* reset_s = (const float*)d_in[6];  // reset_s [32,512,256]
    const int*   t1      = (const int*)d_in[7];    // t1 scalar
    float* out = (float*)d_out;

    (void)in_sizes; (void)n_in; (void)out_size;
    snn_kernel<<<NSAMP / WPB, WPB * 32>>>(ic, w, mu, v0, i0, s0, reset_s, t1, out);
}